// round 15
// baseline (speedup 1.0000x reference)
#include <cuda_runtime.h>
#include <cuda_bf16.h>
#include <math.h>

#define TT   1024
#define TOPK 256
#define NEGF (-1e30f)

// ---------------------------------------------------------------------------
// Scratch (device globals; no cudaMalloc allowed)
// ---------------------------------------------------------------------------
#define OFF_QLAT   0UL
#define OFF_CKV    1572864UL
#define OFF_SKV    2162688UL
#define OFF_QI     2753088UL
#define OFF_KI     4850240UL
#define OFF_W      4981312UL
#define OFF_SCORE  4997696UL
#define OFF_IDX    6046272UL
#define OFF_QFULL  6308416UL
#define OFF_SQ     9454144UL
#define OFF_ATTN   18891328UL
#define OFF_O      27279936UL
#define SCRATCH_FLOATS 29377088UL

__device__ float g_scratch[SCRATCH_FLOATS];

// ---------------------------------------------------------------------------
// Streams/events for DAG overlap
// ---------------------------------------------------------------------------
struct StreamPack {
    cudaStream_t s1, s2;
    cudaEvent_t e_start, e_qlat, e_ki, e_kv, e_sq;
    StreamPack() {
        cudaStreamCreateWithFlags(&s1, cudaStreamNonBlocking);
        cudaStreamCreateWithFlags(&s2, cudaStreamNonBlocking);
        cudaEventCreateWithFlags(&e_start, cudaEventDisableTiming);
        cudaEventCreateWithFlags(&e_qlat, cudaEventDisableTiming);
        cudaEventCreateWithFlags(&e_ki,   cudaEventDisableTiming);
        cudaEventCreateWithFlags(&e_kv,   cudaEventDisableTiming);
        cudaEventCreateWithFlags(&e_sq,   cudaEventDisableTiming);
    }
};
static StreamPack g_sp;

// ---------------------------------------------------------------------------
// fp64 block reduction for norm statistics
// ---------------------------------------------------------------------------
__device__ __forceinline__ double block_reduce_sum_d(double v, double* sm) {
    int lane = threadIdx.x & 31, wid = threadIdx.x >> 5;
#pragma unroll
    for (int o = 16; o > 0; o >>= 1) v += __shfl_xor_sync(0xffffffffu, v, o);
    if (lane == 0) sm[wid] = v;
    __syncthreads();
    int nw = (blockDim.x + 31) >> 5;
    double r = (threadIdx.x < nw) ? sm[threadIdx.x] : 0.0;
#pragma unroll
    for (int o = 16; o > 0; o >>= 1) r += __shfl_xor_sync(0xffffffffu, r, o);
    if (threadIdx.x == 0) sm[0] = r;
    __syncthreads();
    r = sm[0];
    __syncthreads();
    return r;
}

__device__ __forceinline__ float rsqrt_exact(float x) {
    return __fdiv_rn(1.0f, __fsqrt_rn(x));
}

// XOR swizzle of 16B granules within 128B blocks
__device__ __forceinline__ int sw8(int row, int g) {
    return (g & ~7) | ((g ^ row) & 7);
}

// ---------------------------------------------------------------------------
// SCORE GEMM: 64x64 tile, 8x4 micro-tile, 128 threads, register double-buffer.
// fp32 chains over 32-k chunks folded into doubles (bit-identical to R13).
// B is [N,K] row-major.
// ---------------------------------------------------------------------------
__global__ __launch_bounds__(128)
void gemm_score_kernel(const float* __restrict__ A, const float* __restrict__ B,
                       float* __restrict__ C,
                       int M, int N, int K, int lda, int ldb, int ldc) {
    __shared__ float As[16 * 68];
    __shared__ float Bs[16 * 68];
    int m0 = blockIdx.y * 64, n0 = blockIdx.x * 64;
    int tid = threadIdx.x;
    int tx = tid & 15, ty = tid >> 4;   // ty 0..7

    float  accf[8][4];
    double accd[8][4];
#pragma unroll
    for (int i = 0; i < 8; i++)
#pragma unroll
        for (int j = 0; j < 4; j++) { accf[i][j] = 0.f; accd[i][j] = 0.0; }

    float4 ra[2], rb[2];
#pragma unroll
    for (int i = 0; i < 2; i++) {
        int e = tid + i * 128;
        int kg = (e & 3) << 2, r = e >> 2;
        ra[i] = make_float4(0.f, 0.f, 0.f, 0.f);
        if (m0 + r < M)
            ra[i] = *reinterpret_cast<const float4*>(&A[(long long)(m0 + r) * lda + kg]);
        rb[i] = make_float4(0.f, 0.f, 0.f, 0.f);
        if (n0 + r < N)
            rb[i] = *reinterpret_cast<const float4*>(&B[(long long)(n0 + r) * ldb + kg]);
    }

    for (int k0 = 0; k0 < K; k0 += 16) {
#pragma unroll
        for (int i = 0; i < 2; i++) {
            int e = tid + i * 128;
            int kg = (e & 3) << 2, r = e >> 2;
            As[(kg + 0) * 68 + r] = ra[i].x;
            As[(kg + 1) * 68 + r] = ra[i].y;
            As[(kg + 2) * 68 + r] = ra[i].z;
            As[(kg + 3) * 68 + r] = ra[i].w;
            Bs[(kg + 0) * 68 + r] = rb[i].x;
            Bs[(kg + 1) * 68 + r] = rb[i].y;
            Bs[(kg + 2) * 68 + r] = rb[i].z;
            Bs[(kg + 3) * 68 + r] = rb[i].w;
        }
        __syncthreads();
        int kn = k0 + 16;
        if (kn < K) {
#pragma unroll
            for (int i = 0; i < 2; i++) {
                int e = tid + i * 128;
                int kg = (e & 3) << 2, r = e >> 2;
                ra[i] = make_float4(0.f, 0.f, 0.f, 0.f);
                if (m0 + r < M)
                    ra[i] = *reinterpret_cast<const float4*>(&A[(long long)(m0 + r) * lda + kn + kg]);
                rb[i] = make_float4(0.f, 0.f, 0.f, 0.f);
                if (n0 + r < N)
                    rb[i] = *reinterpret_cast<const float4*>(&B[(long long)(n0 + r) * ldb + kn + kg]);
            }
        }
#pragma unroll
        for (int kk = 0; kk < 16; kk++) {
            float4 a0 = *reinterpret_cast<const float4*>(&As[kk * 68 + ty * 8]);
            float4 a1 = *reinterpret_cast<const float4*>(&As[kk * 68 + ty * 8 + 4]);
            float4 b4 = *reinterpret_cast<const float4*>(&Bs[kk * 68 + tx * 4]);
            float a[8] = {a0.x, a0.y, a0.z, a0.w, a1.x, a1.y, a1.z, a1.w};
            float b[4] = {b4.x, b4.y, b4.z, b4.w};
#pragma unroll
            for (int i = 0; i < 8; i++)
#pragma unroll
                for (int j = 0; j < 4; j++)
                    accf[i][j] = fmaf(a[i], b[j], accf[i][j]);
        }
        if ((k0 >> 4) & 1) {
#pragma unroll
            for (int i = 0; i < 8; i++)
#pragma unroll
                for (int j = 0; j < 4; j++) {
                    accd[i][j] += (double)accf[i][j];
                    accf[i][j] = 0.f;
                }
        }
        __syncthreads();
    }
#pragma unroll
    for (int i = 0; i < 8; i++) {
        int m = m0 + ty * 8 + i;
        if (m >= M) continue;
        int n = n0 + tx * 4;
        float o0 = (float)accd[i][0], o1 = (float)accd[i][1];
        float o2 = (float)accd[i][2], o3 = (float)accd[i][3];
        if (n + 3 < N) {
            *reinterpret_cast<float4*>(&C[(long long)m * ldc + n]) = make_float4(o0, o1, o2, o3);
        } else {
            if (n + 0 < N) C[(long long)m * ldc + n + 0] = o0;
            if (n + 1 < N) C[(long long)m * ldc + n + 1] = o1;
            if (n + 2 < N) C[(long long)m * ldc + n + 2] = o2;
            if (n + 3 < N) C[(long long)m * ldc + n + 3] = o3;
        }
    }
}

// ---------------------------------------------------------------------------
// 128x128 GEMM (B is [N,K]), 8x8 micro-tile, register double-buffer, fp32.
// ---------------------------------------------------------------------------
__global__ __launch_bounds__(256)
void gemm128_kernel(const float* __restrict__ A, const float* __restrict__ B,
                    float* __restrict__ C,
                    int M, int N, int K, int lda, int ldb, int ldc) {
    __shared__ float As[16 * 132];
    __shared__ float Bs[16 * 132];
    int m0 = blockIdx.y * 128, n0 = blockIdx.x * 128;
    int tid = threadIdx.x;
    int tx = tid & 15, ty = tid >> 4;

    float acc[8][8];
#pragma unroll
    for (int i = 0; i < 8; i++)
#pragma unroll
        for (int j = 0; j < 8; j++) acc[i][j] = 0.f;

    float4 ra[2], rb[2];
#pragma unroll
    for (int i = 0; i < 2; i++) {
        int e = tid + i * 256;
        int kg = (e & 3) << 2, r = e >> 2;
        ra[i] = make_float4(0.f, 0.f, 0.f, 0.f);
        if (m0 + r < M)
            ra[i] = *reinterpret_cast<const float4*>(&A[(long long)(m0 + r) * lda + kg]);
        rb[i] = make_float4(0.f, 0.f, 0.f, 0.f);
        if (n0 + r < N)
            rb[i] = *reinterpret_cast<const float4*>(&B[(long long)(n0 + r) * ldb + kg]);
    }

    for (int k0 = 0; k0 < K; k0 += 16) {
#pragma unroll
        for (int i = 0; i < 2; i++) {
            int e = tid + i * 256;
            int kg = (e & 3) << 2, r = e >> 2;
            As[(kg + 0) * 132 + r] = ra[i].x;
            As[(kg + 1) * 132 + r] = ra[i].y;
            As[(kg + 2) * 132 + r] = ra[i].z;
            As[(kg + 3) * 132 + r] = ra[i].w;
            Bs[(kg + 0) * 132 + r] = rb[i].x;
            Bs[(kg + 1) * 132 + r] = rb[i].y;
            Bs[(kg + 2) * 132 + r] = rb[i].z;
            Bs[(kg + 3) * 132 + r] = rb[i].w;
        }
        __syncthreads();
        int kn = k0 + 16;
        if (kn < K) {
#pragma unroll
            for (int i = 0; i < 2; i++) {
                int e = tid + i * 256;
                int kg = (e & 3) << 2, r = e >> 2;
                ra[i] = make_float4(0.f, 0.f, 0.f, 0.f);
                if (m0 + r < M)
                    ra[i] = *reinterpret_cast<const float4*>(&A[(long long)(m0 + r) * lda + kn + kg]);
                rb[i] = make_float4(0.f, 0.f, 0.f, 0.f);
                if (n0 + r < N)
                    rb[i] = *reinterpret_cast<const float4*>(&B[(long long)(n0 + r) * ldb + kn + kg]);
            }
        }
#pragma unroll
        for (int kk = 0; kk < 16; kk++) {
            float4 a0 = *reinterpret_cast<const float4*>(&As[kk * 132 + ty * 8]);
            float4 a1 = *reinterpret_cast<const float4*>(&As[kk * 132 + ty * 8 + 4]);
            float4 b0 = *reinterpret_cast<const float4*>(&Bs[kk * 132 + tx * 8]);
            float4 b1 = *reinterpret_cast<const float4*>(&Bs[kk * 132 + tx * 8 + 4]);
            float a[8] = {a0.x, a0.y, a0.z, a0.w, a1.x, a1.y, a1.z, a1.w};
            float b[8] = {b0.x, b0.y, b0.z, b0.w, b1.x, b1.y, b1.z, b1.w};
#pragma unroll
            for (int i = 0; i < 8; i++)
#pragma unroll
                for (int j = 0; j < 8; j++)
                    acc[i][j] = fmaf(a[i], b[j], acc[i][j]);
        }
        __syncthreads();
    }
#pragma unroll
    for (int i = 0; i < 8; i++) {
        int m = m0 + ty * 8 + i;
        if (m >= M) continue;
        int n = n0 + tx * 8;
        if (n + 7 < N) {
            *reinterpret_cast<float4*>(&C[(long long)m * ldc + n]) =
                make_float4(acc[i][0], acc[i][1], acc[i][2], acc[i][3]);
            *reinterpret_cast<float4*>(&C[(long long)m * ldc + n + 4]) =
                make_float4(acc[i][4], acc[i][5], acc[i][6], acc[i][7]);
        } else {
#pragma unroll
            for (int j = 0; j < 8; j++)
                if (n + j < N) C[(long long)m * ldc + n + j] = acc[i][j];
        }
    }
}

// ---------------------------------------------------------------------------
// VALUE-PATH GEMM: 128x64 tile, 8x4 micro-tile, fp32, register double-buffer.
// ---------------------------------------------------------------------------
template<bool BT>
__global__ __launch_bounds__(256)
void gemm_kernel(const float* __restrict__ A, const float* __restrict__ B,
                 float* __restrict__ C,
                 int M, int N, int K, int lda, int ldb, int ldc,
                 long long sA, long long sB, long long sC) {
    __shared__ float As[16 * 132];
    __shared__ float Bs[16 * 68];
    long long bz = blockIdx.z;
    A += bz * sA; B += bz * sB; C += bz * sC;
    int m0 = blockIdx.y * 128, n0 = blockIdx.x * 64;
    int tid = threadIdx.x;
    int tx = tid & 15, ty = tid >> 4;

    float acc[8][4];
#pragma unroll
    for (int i = 0; i < 8; i++)
#pragma unroll
        for (int j = 0; j < 4; j++) acc[i][j] = 0.f;

    float4 ra[2], rb;
#pragma unroll
    for (int i = 0; i < 2; i++) {
        int e = tid + i * 256;
        int kg = (e & 3) << 2, m = e >> 2;
        ra[i] = make_float4(0.f, 0.f, 0.f, 0.f);
        if (m0 + m < M)
            ra[i] = *reinterpret_cast<const float4*>(&A[(long long)(m0 + m) * lda + kg]);
    }
    if (BT) {
        int kg = (tid & 3) << 2, n = tid >> 2;
        rb = make_float4(0.f, 0.f, 0.f, 0.f);
        if (n0 + n < N)
            rb = *reinterpret_cast<const float4*>(&B[(long long)(n0 + n) * ldb + kg]);
    } else {
        int ng = (tid & 15) << 2, kk = tid >> 4;
        rb = make_float4(0.f, 0.f, 0.f, 0.f);
        if (n0 + ng < N)
            rb = *reinterpret_cast<const float4*>(&B[(long long)kk * ldb + n0 + ng]);
    }

    for (int k0 = 0; k0 < K; k0 += 16) {
#pragma unroll
        for (int i = 0; i < 2; i++) {
            int e = tid + i * 256;
            int kg = (e & 3) << 2, m = e >> 2;
            As[(kg + 0) * 132 + m] = ra[i].x;
            As[(kg + 1) * 132 + m] = ra[i].y;
            As[(kg + 2) * 132 + m] = ra[i].z;
            As[(kg + 3) * 132 + m] = ra[i].w;
        }
        if (BT) {
            int kg = (tid & 3) << 2, n = tid >> 2;
            Bs[(kg + 0) * 68 + n] = rb.x;
            Bs[(kg + 1) * 68 + n] = rb.y;
            Bs[(kg + 2) * 68 + n] = rb.z;
            Bs[(kg + 3) * 68 + n] = rb.w;
        } else {
            int ng = (tid & 15) << 2, kk = tid >> 4;
            *reinterpret_cast<float4*>(&Bs[kk * 68 + ng]) = rb;
        }
        __syncthreads();
        int kn = k0 + 16;
        if (kn < K) {
#pragma unroll
            for (int i = 0; i < 2; i++) {
                int e = tid + i * 256;
                int kg = (e & 3) << 2, m = e >> 2;
                ra[i] = make_float4(0.f, 0.f, 0.f, 0.f);
                if (m0 + m < M)
                    ra[i] = *reinterpret_cast<const float4*>(&A[(long long)(m0 + m) * lda + kn + kg]);
            }
            if (BT) {
                int kg = (tid & 3) << 2, n = tid >> 2;
                rb = make_float4(0.f, 0.f, 0.f, 0.f);
                if (n0 + n < N)
                    rb = *reinterpret_cast<const float4*>(&B[(long long)(n0 + n) * ldb + kn + kg]);
            } else {
                int ng = (tid & 15) << 2, kk = tid >> 4;
                rb = make_float4(0.f, 0.f, 0.f, 0.f);
                if (n0 + ng < N)
                    rb = *reinterpret_cast<const float4*>(&B[(long long)(kn + kk) * ldb + n0 + ng]);
            }
        }
#pragma unroll
        for (int kk = 0; kk < 16; kk++) {
            float4 a0 = *reinterpret_cast<const float4*>(&As[kk * 132 + ty * 8]);
            float4 a1 = *reinterpret_cast<const float4*>(&As[kk * 132 + ty * 8 + 4]);
            float4 b4 = *reinterpret_cast<const float4*>(&Bs[kk * 68 + tx * 4]);
            float a[8] = {a0.x, a0.y, a0.z, a0.w, a1.x, a1.y, a1.z, a1.w};
            float b[4] = {b4.x, b4.y, b4.z, b4.w};
#pragma unroll
            for (int i = 0; i < 8; i++)
#pragma unroll
                for (int j = 0; j < 4; j++)
                    acc[i][j] = fmaf(a[i], b[j], acc[i][j]);
        }
        __syncthreads();
    }
#pragma unroll
    for (int i = 0; i < 8; i++) {
        int m = m0 + ty * 8 + i;
        if (m >= M) continue;
        int n = n0 + tx * 4;
        if (n + 3 < N) {
            *reinterpret_cast<float4*>(&C[(long long)m * ldc + n]) =
                make_float4(acc[i][0], acc[i][1], acc[i][2], acc[i][3]);
        } else {
#pragma unroll
            for (int j = 0; j < 4; j++)
                if (n + j < N) C[(long long)m * ldc + n + j] = acc[i][j];
        }
    }
}

// ---------------------------------------------------------------------------
// 64x64 GEMM, 4x4 micro-tile, fp32 (value path; small grids)
// ---------------------------------------------------------------------------
__global__ __launch_bounds__(256)
void gemm64f_kernel(const float* __restrict__ A, const float* __restrict__ B,
                    float* __restrict__ C,
                    int M, int N, int K, int lda, int ldb, int ldc) {
    __shared__ float As[16 * 68];
    __shared__ float Bs[16 * 68];
    int m0 = blockIdx.y * 64, n0 = blockIdx.x * 64;
    int tid = threadIdx.x;
    int tx = tid & 15, ty = tid >> 4;

    float accf[4][4];
#pragma unroll
    for (int i = 0; i < 4; i++)
#pragma unroll
        for (int j = 0; j < 4; j++) accf[i][j] = 0.f;

    int kg = (tid & 3) << 2, mrow = tid >> 2;
    float4 ra, rb;
    ra = make_float4(0.f, 0.f, 0.f, 0.f);
    if (m0 + mrow < M)
        ra = *reinterpret_cast<const float4*>(&A[(long long)(m0 + mrow) * lda + kg]);
    rb = make_float4(0.f, 0.f, 0.f, 0.f);
    if (n0 + mrow < N)
        rb = *reinterpret_cast<const float4*>(&B[(long long)(n0 + mrow) * ldb + kg]);

    for (int k0 = 0; k0 < K; k0 += 16) {
        As[(kg + 0) * 68 + mrow] = ra.x;
        As[(kg + 1) * 68 + mrow] = ra.y;
        As[(kg + 2) * 68 + mrow] = ra.z;
        As[(kg + 3) * 68 + mrow] = ra.w;
        Bs[(kg + 0) * 68 + mrow] = rb.x;
        Bs[(kg + 1) * 68 + mrow] = rb.y;
        Bs[(kg + 2) * 68 + mrow] = rb.z;
        Bs[(kg + 3) * 68 + mrow] = rb.w;
        __syncthreads();
        int kn = k0 + 16;
        if (kn < K) {
            ra = make_float4(0.f, 0.f, 0.f, 0.f);
            if (m0 + mrow < M)
                ra = *reinterpret_cast<const float4*>(&A[(long long)(m0 + mrow) * lda + kn + kg]);
            rb = make_float4(0.f, 0.f, 0.f, 0.f);
            if (n0 + mrow < N)
                rb = *reinterpret_cast<const float4*>(&B[(long long)(n0 + mrow) * ldb + kn + kg]);
        }
#pragma unroll
        for (int kk = 0; kk < 16; kk++) {
            float4 a4 = *reinterpret_cast<const float4*>(&As[kk * 68 + ty * 4]);
            float4 b4 = *reinterpret_cast<const float4*>(&Bs[kk * 68 + tx * 4]);
            float a[4] = {a4.x, a4.y, a4.z, a4.w};
            float b[4] = {b4.x, b4.y, b4.z, b4.w};
#pragma unroll
            for (int i = 0; i < 4; i++)
#pragma unroll
                for (int j = 0; j < 4; j++)
                    accf[i][j] = fmaf(a[i], b[j], accf[i][j]);
        }
        __syncthreads();
    }
#pragma unroll
    for (int i = 0; i < 4; i++) {
        int m = m0 + ty * 4 + i;
        if (m >= M) continue;
        int n = n0 + tx * 4;
        if (n + 3 < N) {
            *reinterpret_cast<float4*>(&C[(long long)m * ldc + n]) =
                make_float4(accf[i][0], accf[i][1], accf[i][2], accf[i][3]);
        } else {
#pragma unroll
            for (int j = 0; j < 4; j++)
                if (n + j < N) C[(long long)m * ldc + n + j] = accf[i][j];
        }
    }
}

// ---------------------------------------------------------------------------
// RMSNorm rows in-place (fp64 stats, exact f32 epilogue)
// ---------------------------------------------------------------------------
__global__ void rms_kernel(float* x, const float* __restrict__ g, int N) {
    __shared__ double sm[8];
    int t = blockIdx.x;
    float* row = x + (size_t)t * N;
    double s = 0.0;
    for (int i = threadIdx.x; i < N; i += blockDim.x) { double v = row[i]; s += v * v; }
    s = block_reduce_sum_d(s, sm);
    float mean = __fdiv_rn((float)s, (float)N);
    float inv = rsqrt_exact(__fadd_rn(mean, 1e-6f));
    for (int i = threadIdx.x; i < N; i += blockDim.x)
        row[i] = __fmul_rn(__fmul_rn(row[i], inv), g[i]);
}

// ---------------------------------------------------------------------------
// Build skv[1025][576]
// ---------------------------------------------------------------------------
__global__ void kv_kernel(const float* __restrict__ ckv, const float* __restrict__ g,
                          const float* __restrict__ cosb, const float* __restrict__ sinb,
                          float* __restrict__ skv) {
    int t = blockIdx.x;
    if (t == TT) {
        for (int i = threadIdx.x; i < 576; i += blockDim.x) skv[(size_t)TT * 576 + i] = 0.f;
        return;
    }
    __shared__ double sm[8];
    const float* row = ckv + (size_t)t * 576;
    double s = 0.0;
    for (int i = threadIdx.x; i < 512; i += blockDim.x) { double v = row[i]; s += v * v; }
    s = block_reduce_sum_d(s, sm);
    float mean = __fdiv_rn((float)s, 512.f);
    float inv = rsqrt_exact(__fadd_rn(mean, 1e-6f));
    for (int i = threadIdx.x; i < 512; i += blockDim.x)
        skv[(size_t)t * 576 + i] = __fmul_rn(__fmul_rn(row[i], inv), g[i]);
    if (threadIdx.x < 64) {
        int i = threadIdx.x;
        float c = cosb[t * 64 + i], sn = sinb[t * 64 + i];
        float o;
        if (i < 32) o = __fsub_rn(__fmul_rn(row[512 + 2 * i], c), __fmul_rn(row[512 + 2 * i + 1], sn));
        else { int j = i - 32; o = __fadd_rn(__fmul_rn(row[512 + 2 * j + 1], c), __fmul_rn(row[512 + 2 * j], sn)); }
        skv[(size_t)t * 576 + 512 + i] = o;
    }
}

// ---------------------------------------------------------------------------
// In-place rope on first 64 dims of each 128-dim indexer head
// ---------------------------------------------------------------------------
__global__ void qirope_kernel(float* qi, const float* __restrict__ cosb,
                              const float* __restrict__ sinb) {
    int t = blockIdx.x;
    int h = threadIdx.x >> 5, lane = threadIdx.x & 31;
    float* p = qi + (size_t)t * 2048 + h * 128;
    float x0 = p[2 * lane], x1 = p[2 * lane + 1];
    float c0 = cosb[t * 64 + lane], s0 = sinb[t * 64 + lane];
    float c1 = cosb[t * 64 + 32 + lane], s1 = sinb[t * 64 + 32 + lane];
    __syncwarp();
    p[lane]      = __fsub_rn(__fmul_rn(x0, c0), __fmul_rn(x1, s0));
    p[lane + 32] = __fadd_rn(__fmul_rn(x1, c1), __fmul_rn(x0, s1));
}

// ---------------------------------------------------------------------------
// In-place LayerNorm(128)+rope on ki rows (fp64 stats, exact f32 epilogue)
// ---------------------------------------------------------------------------
__global__ void ki_kernel(float* ki, const float* __restrict__ w, const float* __restrict__ b,
                          const float* __restrict__ cosb, const float* __restrict__ sinb) {
    __shared__ double sm[8];
    __shared__ float srow[128];
    int t = blockIdx.x, d = threadIdx.x;
    float* row = ki + (size_t)t * 128;
    float v = row[d];
    double msum = block_reduce_sum_d((double)v, sm);
    float m = __fdiv_rn((float)msum, 128.f);
    float dv = __fsub_rn(v, m);
    double vsum = block_reduce_sum_d((double)dv * (double)dv, sm);
    float var = __fdiv_rn((float)vsum, 128.f);
    float inv = rsqrt_exact(__fadd_rn(var, 1e-6f));
    float y = __fadd_rn(__fmul_rn(__fmul_rn(dv, inv), w[d]), b[d]);
    srow[d] = y;
    __syncthreads();
    float o;
    if (d < 32)
        o = __fsub_rn(__fmul_rn(srow[2 * d], cosb[t * 64 + d]), __fmul_rn(srow[2 * d + 1], sinb[t * 64 + d]));
    else if (d < 64) {
        int j = d - 32;
        o = __fadd_rn(__fmul_rn(srow[2 * j + 1], cosb[t * 64 + d]), __fmul_rn(srow[2 * j], sinb[t * 64 + d]));
    } else o = y;
    row[d] = o;
}

// ---------------------------------------------------------------------------
// Indexer score: 8 t per block, causal skip.
// ---------------------------------------------------------------------------
__global__ __launch_bounds__(256)
void score_kernel(const float* __restrict__ qi, const float* __restrict__ ki,
                  const float* __restrict__ wproj,
                  const int* __restrict__ ks, const int* __restrict__ ke,
                  float* __restrict__ score) {
    __shared__ float s_qi[16 * 132];
    __shared__ float s_ki[16 * 132];
    __shared__ float s_prod[16 * 16];
    int s0 = blockIdx.x * 16;
    int h = threadIdx.x & 15, sl = threadIdx.x >> 4;
    bool ki_loaded = false;
    for (int tt = 0; tt < 8; tt++) {
        int t = blockIdx.y * 8 + tt;
        int kst = ks[t], ket = ke[t];
        if (ket - kst + 1 <= TOPK) continue;
        if (s0 > ket || s0 + 15 < kst) {
            if (threadIdx.x < 16)
                score[(size_t)t * TT + s0 + threadIdx.x] = NEGF;
            continue;
        }
        if (!ki_loaded) {
#pragma unroll
            for (int i = 0; i < 2; i++) {
                int e = threadIdx.x + i * 256;
                int r = e >> 5, c4 = (e & 31) << 2;
                *reinterpret_cast<float4*>(&s_ki[r * 132 + c4]) =
                    *reinterpret_cast<const float4*>(&ki[(size_t)(s0 + r) * 128 + c4]);
            }
            ki_loaded = true;
        }
        __syncthreads();
#pragma unroll
        for (int i = 0; i < 2; i++) {
            int e = threadIdx.x + i * 256;
            int r = e >> 5, c4 = (e & 31) << 2;
            *reinterpret_cast<float4*>(&s_qi[r * 132 + c4]) =
                *reinterpret_cast<const float4*>(&qi[(size_t)t * 2048 + r * 128 + c4]);
        }
        __syncthreads();
        double acc = 0.0;
#pragma unroll
        for (int c0 = 0; c0 < 128; c0 += 32) {
            float tacc = 0.f;
#pragma unroll
            for (int d4 = 0; d4 < 8; d4++) {
                float4 q4 = *reinterpret_cast<const float4*>(&s_qi[h * 132 + c0 + d4 * 4]);
                float4 k4 = *reinterpret_cast<const float4*>(&s_ki[sl * 132 + c0 + d4 * 4]);
                tacc = fmaf(q4.x, k4.x, tacc);
                tacc = fmaf(q4.y, k4.y, tacc);
                tacc = fmaf(q4.z, k4.z, tacc);
                tacc = fmaf(q4.w, k4.w, tacc);
            }
            acc += (double)tacc;
        }
        float lg = (float)acc;
        s_prod[sl * 16 + h] = __fmul_rn(fmaxf(lg, 0.f), wproj[t * 16 + h]);
        __syncthreads();
        if (threadIdx.x < 16) {
            int s = s0 + threadIdx.x;
            double sum = 0.0;
#pragma unroll
            for (int hh = 0; hh < 16; hh++) sum += (double)s_prod[threadIdx.x * 16 + hh];
            float sc = __fmul_rn((float)sum, 0.022097086912079608f);
            if (s < kst || s > ket) sc = NEGF;
            score[(size_t)t * TT + s] = sc;
        }
    }
}

// ---------------------------------------------------------------------------
// Top-256 per row; trivial rows short-circuited.
// ---------------------------------------------------------------------------
__global__ __launch_bounds__(512)
void topk_kernel(const float* __restrict__ score, const int* __restrict__ ks,
                 const int* __restrict__ ke, int* __restrict__ out) {
    __shared__ unsigned long long keys[TT];
    int t = blockIdx.x;
    int kst = ks[t], ket = ke[t];
    int nvalid = ket - kst + 1;
    if (nvalid <= TOPK) {
        if (threadIdx.x < TOPK) {
            int j = threadIdx.x;
            out[t * TOPK + j] = (j < nvalid) ? (kst + j) : TT;
        }
        return;
    }
    const float* row = score + (size_t)t * TT;
    for (int i = threadIdx.x; i < TT; i += 512) {
        unsigned u = __float_as_uint(row[i]);
        if (u == 0x80000000u) u = 0u;
        u = (u & 0x80000000u) ? ~u : (u | 0x80000000u);
        keys[i] = ((unsigned long long)(~u) << 32) | (unsigned)i;
    }
    __syncthreads();
    for (int k = 2; k <= TT; k <<= 1) {
        for (int j = k >> 1; j > 0; j >>= 1) {
            for (int i = threadIdx.x; i < TT; i += 512) {
                int ixj = i ^ j;
                if (ixj > i) {
                    bool up = ((i & k) == 0);
                    unsigned long long a = keys[i], c = keys[ixj];
                    if ((a > c) == up) { keys[i] = c; keys[ixj] = a; }
                }
            }
            __syncthreads();
        }
    }
    if (threadIdx.x < TOPK) {
        int idx = (int)(keys[threadIdx.x] & 0xffffffffu);
        float v = score[(size_t)t * TT + idx];
        out[t * TOPK + threadIdx.x] = (v <= -5e29f) ? TT : idx;
    }
}

// ---------------------------------------------------------------------------
// Fill sq[t,h,512:576] = rope(q_full[t, h*192+128 : h*192+192])
// ---------------------------------------------------------------------------
__global__ void sqrope_kernel(const float* __restrict__ qfull, const float* __restrict__ cosb,
                              const float* __restrict__ sinb, float* __restrict__ sq) {
    int t = blockIdx.x;
    int h = threadIdx.x >> 5, lane = threadIdx.x & 31;
    const float* p = qfull + (size_t)t * 3072 + h * 192 + 128;
    float x0 = p[2 * lane], x1 = p[2 * lane + 1];
    float* o = sq + ((size_t)t * 16 + h) * 576 + 512;
    o[lane]      = __fsub_rn(__fmul_rn(x0, cosb[t * 64 + lane]), __fmul_rn(x1, sinb[t * 64 + lane]));
    o[lane + 32] = __fadd_rn(__fmul_rn(x1, cosb[t * 64 + 32 + lane]), __fmul_rn(x0, sinb[t * 64 + 32 + lane]));
}

// ---------------------------------------------------------------------------
// Gathered sparse attention — online softmax, prefetched gather, XOR-swizzled
// smem (stride 576, granule swizzle sw8) to hit the LDS bandwidth floor.
// ---------------------------------------------------------------------------
#define ATT_SMEM ((16*576*2) * 4 + 256 * 4)
__global__ __launch_bounds__(256, 2)
void attn_kernel(const float* __restrict__ sq, const float* __restrict__ skv,
                 const int* __restrict__ idxs, float* __restrict__ out) {
    extern __shared__ float sm[];
    float* s_sq = sm;                     // 16 x 144 granules, swizzled
    float* s_kv = sm + 16 * 576;
    int*   s_idx = (int*)(sm + 2 * 16 * 576);
    int t = blockIdx.x, tid = threadIdx.x;
    int h = tid >> 4, q = tid & 15;

    s_idx[tid] = idxs[t * TOPK + tid];
#pragma unroll
    for (int i = 0; i < 9; i++) {
        int e = tid + i * 256;
        int r = e / 144, g = e % 144;
        *reinterpret_cast<float4*>(&s_sq[r * 576 + sw8(r, g) * 4]) =
            *reinterpret_cast<const float4*>(&sq[(size_t)t * 9216 + r * 576 + g * 4]);
    }
    __syncthreads();

    float4 pre[9];
#pragma unroll
    for (int i = 0; i < 9; i++) {
        int e = tid + i * 256;
        int r = e / 144, g = e % 144;
        int gi = s_idx[r];
        pre[i] = *reinterpret_cast<const float4*>(&skv[(size_t)gi * 576 + g * 4]);
    }

    const float qscale = 0.07216878364870323f;
    float m_run = NEGF, s_run = 0.f;
    float acc2[32];
#pragma unroll
    for (int i = 0; i < 32; i++) acc2[i] = 0.f;
    unsigned base16 = tid & 16;

    for (int jb = 0; jb < 16; jb++) {
        __syncthreads();
#pragma unroll
        for (int i = 0; i < 9; i++) {
            int e = tid + i * 256;
            int r = e / 144, g = e % 144;
            *reinterpret_cast<float4*>(&s_kv[r * 576 + sw8(r, g) * 4]) = pre[i];
        }
        if (jb < 15) {
#pragma unroll
            for (int i = 0; i < 9; i++) {
                int e = tid + i * 256;
                int r = e / 144, g = e % 144;
                int gi = s_idx[(jb + 1) * 16 + r];
                pre[i] = *reinterpret_cast<const float4*>(&skv[(size_t)gi * 576 + g * 4]);
            }
        }
        __syncthreads();
        float acc = 0.f;
#pragma unroll 4
        for (int d4 = 0; d4 < 144; d4++) {
            float4 qv = *reinterpret_cast<const float4*>(&s_sq[h * 576 + sw8(h, d4) * 4]);
            float4 kv = *reinterpret_cast<const float4*>(&s_kv[q * 576 + sw8(q, d4) * 4]);
            acc = fmaf(qv.x, kv.x, acc);
            acc = fmaf(qv.y, kv.y, acc);
            acc = fmaf(qv.z, kv.z, acc);
            acc = fmaf(qv.w, kv.w, acc);
        }
        float l = (s_idx[jb * 16 + q] == TT) ? NEGF : acc * qscale;
        float mt = l;
#pragma unroll
        for (int o = 8; o > 0; o >>= 1) mt = fmaxf(mt, __shfl_xor_sync(0xffffffffu, mt, o, 16));
        float m_new = fmaxf(m_run, mt);
        float scale = __expf(m_run - m_new);
        float p = __expf(l - m_new);
        float ps = p;
#pragma unroll
        for (int o = 8; o > 0; o >>= 1) ps += __shfl_xor_sync(0xffffffffu, ps, o, 16);
        s_run = s_run * scale + ps;
        m_run = m_new;
#pragma unroll
        for (int i = 0; i < 32; i++) acc2[i] *= scale;
#pragma unroll 2
        for (int jj = 0; jj < 16; jj++) {
            float pj = __shfl_sync(0xffffffffu, p, base16 + jj, 32);
#pragma unroll
            for (int g = 0; g < 8; g++) {
                int G = g * 16 + q;   // column granule
                float4 kv = *reinterpret_cast<const float4*>(&s_kv[jj * 576 + sw8(jj, G) * 4]);
                acc2[g * 4 + 0] = fmaf(pj, kv.x, acc2[g * 4 + 0]);
                acc2[g * 4 + 1] = fmaf(pj, kv.y, acc2[g * 4 + 1]);
                acc2[g * 4 + 2] = fmaf(pj, kv.z, acc2[g * 4 + 2]);
                acc2[g * 4 + 3] = fmaf(pj, kv.w, acc2[g * 4 + 3]);
            }
        }
    }
    float inv = 1.f / s_run;
    size_t base = ((size_t)t * 16 + h) * 512;
#pragma unroll
    for (int g = 0; g < 8; g++) {
        float4 o = make_float4(acc2[g * 4 + 0] * inv, acc2[g * 4 + 1] * inv,
                               acc2[g * 4 + 2] * inv, acc2[g * 4 + 3] * inv);
        *reinterpret_cast<float4*>(&out[base + g * 64 + (q << 2)]) = o;
    }
}

// ---------------------------------------------------------------------------
// Host launcher — DAG fork/join over 3 streams
// ---------------------------------------------------------------------------
extern "C" void kernel_launch(void* const* d_in, const int* in_sizes, int n_in,
                              void* d_out, int out_size) {
    const float* hidden  = (const float*)d_in[0];
    const float* cosb    = (const float*)d_in[1];
    const float* sinb    = (const float*)d_in[2];
    const int*   ks      = (const int*)d_in[3];
    const int*   ke      = (const int*)d_in[4];
    const float* w_qa    = (const float*)d_in[5];
    const float* g_qa    = (const float*)d_in[6];
    const float* w_qb    = (const float*)d_in[7];
    const float* w_kva   = (const float*)d_in[8];
    const float* g_kva   = (const float*)d_in[9];
    const float* w_kvb   = (const float*)d_in[10];
    const float* w_o     = (const float*)d_in[11];
    const float* i_wqb   = (const float*)d_in[12];
    const float* i_wk    = (const float*)d_in[13];
    const float* i_ln_w  = (const float*)d_in[14];
    const float* i_ln_b  = (const float*)d_in[15];
    const float* i_wproj = (const float*)d_in[16];
    float* out = (float*)d_out;

    void* basev = nullptr;
    cudaGetSymbolAddress(&basev, g_scratch);
    float* base = (float*)basev;
    float* qlat   = base + OFF_QLAT;
    float* ckv    = base + OFF_CKV;
    float* skv    = base + OFF_SKV;
    float* qi     = base + OFF_QI;
    float* ki     = base + OFF_KI;
    float* wbuf   = base + OFF_W;
    float* score  = base + OFF_SCORE;
    int*   idxb   = (int*)(base + OFF_IDX);
    float* qfull  = base + OFF_QFULL;
    float* sq     = base + OFF_SQ;
    float* attnb  = base + OFF_ATTN;
    float* obuf   = base + OFF_O;

    cudaFuncSetAttribute(attn_kernel, cudaFuncAttributeMaxDynamicSharedMemorySize, ATT_SMEM);

    cudaStream_t s0 = 0;
    cudaStream_t s1 = g_sp.s1, s2 = g_sp.s2;
    dim3 blk(256), blk128(128);

    // fork
    cudaEventRecord(g_sp.e_start, s0);
    cudaStreamWaitEvent(s1, g_sp.e_start, 0);
    cudaStreamWaitEvent(s2, g_sp.e_start, 0);

    // --- s2: indexer K/W + KV branch ---
    gemm_score_kernel<<<dim3(2, 16), blk128, 0, s2>>>(hidden, i_wk, ki, 1024, 128, 2048,
                                                      2048, 2048, 128);
    ki_kernel<<<1024, 128, 0, s2>>>(ki, i_ln_w, i_ln_b, cosb, sinb);
    gemm_score_kernel<<<dim3(1, 16), blk128, 0, s2>>>(hidden, i_wproj, wbuf, 1024, 16, 2048,
                                                      2048, 2048, 16);
    cudaEventRecord(g_sp.e_ki, s2);
    gemm64f_kernel<<<dim3(9, 16), blk, 0, s2>>>(hidden, w_kva, ckv, 1024, 576, 2048,
                                                2048, 2048, 576);
    kv_kernel<<<1025, 256, 0, s2>>>(ckv, g_kva, cosb, sinb, skv);
    cudaEventRecord(g_sp.e_kv, s2);

    // --- s0: qlat (critical path) ---
    gemm_score_kernel<<<dim3(24, 16), blk128, 0, s0>>>(hidden, w_qa, qlat, 1024, 1536, 2048,
                                                       2048, 2048, 1536);
    rms_kernel<<<1024, 256, 0, s0>>>(qlat, g_qa, 1536);
    cudaEventRecord(g_sp.e_qlat, s0);

    // --- s1: q_full branch ---
    cudaStreamWaitEvent(s1, g_sp.e_qlat, 0);
    gemm128_kernel<<<dim3(24, 8), blk, 0, s1>>>(qlat, w_qb, qfull, 1024, 3072, 1536,
                                                1536, 1536, 3072);
    gemm_kernel<false><<<dim3(8, 8, 16), blk, 0, s1>>>(qfull, w_kvb, sq, 1024, 512, 128,
                                                       3072, 512, 9216,
                                                       192, 256 * 512, 576);
    sqrope_kernel<<<1024, 512, 0, s1>>>(qfull, cosb, sinb, sq);
    cudaEventRecord(g_sp.e_sq, s1);

    // --- s0: qi -> score -> topk ---
    gemm_score_kernel<<<dim3(32, 16), blk128, 0, s0>>>(qlat, i_wqb, qi, 1024, 2048, 1536,
                                                       1536, 1536, 2048);
    qirope_kernel<<<1024, 512, 0, s0>>>(qi, cosb, sinb);
    cudaStreamWaitEvent(s0, g_sp.e_ki, 0);
    score_kernel<<<dim3(64, 128), blk, 0, s0>>>(qi, ki, wbuf, ks, ke, score);
    topk_kernel<<<1024, 512, 0, s0>>>(score, ks, ke, idxb);

    // --- join: attention + output projections ---
    cudaStreamWaitEvent(s0, g_sp.e_kv, 0);
    cudaStreamWaitEvent(s0, g_sp.e_sq, 0);
    attn_kernel<<<1024, 256, ATT_SMEM, s0>>>(sq, skv, idxb, attnb);
    gemm_kernel<true><<<dim3(2, 8, 16), blk, 0, s0>>>(attnb, w_kvb + 128 * 512, obuf,
                                                      1024, 128, 512,
                                                      8192, 512, 2048,
                                                      512, 256 * 512, 128);
    gemm128_kernel<<<dim3(16, 8), blk, 0, s0>>>(obuf, w_o, out, 1024, 2048, 2048,
                                                2048, 2048, 2048);
}

// round 16
// speedup vs baseline: 1.1843x; 1.1843x over previous
#include <cuda_runtime.h>
#include <cuda_bf16.h>
#include <math.h>

#define TT   1024
#define TOPK 256
#define NEGF (-1e30f)

// ---------------------------------------------------------------------------
// Scratch (device globals; no cudaMalloc allowed)
// ---------------------------------------------------------------------------
#define OFF_QLAT   0UL
#define OFF_CKV    1572864UL
#define OFF_SKV    2162688UL
#define OFF_QI     2753088UL
#define OFF_KI     4850240UL
#define OFF_W      4981312UL
#define OFF_SCORE  4997696UL
#define OFF_IDX    6046272UL
#define OFF_QFULL  6308416UL
#define OFF_SQ     9454144UL
#define OFF_ATTN   18891328UL
#define OFF_O      27279936UL
#define SCRATCH_FLOATS 29377088UL

__device__ float g_scratch[SCRATCH_FLOATS];

// ---------------------------------------------------------------------------
// Streams/events for DAG overlap — host-side resources, created at module init
// ---------------------------------------------------------------------------
struct StreamPack {
    cudaStream_t s1, s2;
    cudaEvent_t e_start, e_qlat, e_ki, e_kv, e_sq;
    StreamPack() {
        cudaStreamCreateWithFlags(&s1, cudaStreamNonBlocking);
        cudaStreamCreateWithFlags(&s2, cudaStreamNonBlocking);
        cudaEventCreateWithFlags(&e_start, cudaEventDisableTiming);
        cudaEventCreateWithFlags(&e_qlat, cudaEventDisableTiming);
        cudaEventCreateWithFlags(&e_ki,   cudaEventDisableTiming);
        cudaEventCreateWithFlags(&e_kv,   cudaEventDisableTiming);
        cudaEventCreateWithFlags(&e_sq,   cudaEventDisableTiming);
    }
};
static StreamPack g_sp;

// ---------------------------------------------------------------------------
// fp64 block reduction for norm statistics
// ---------------------------------------------------------------------------
__device__ __forceinline__ double block_reduce_sum_d(double v, double* sm) {
    int lane = threadIdx.x & 31, wid = threadIdx.x >> 5;
#pragma unroll
    for (int o = 16; o > 0; o >>= 1) v += __shfl_xor_sync(0xffffffffu, v, o);
    if (lane == 0) sm[wid] = v;
    __syncthreads();
    int nw = (blockDim.x + 31) >> 5;
    double r = (threadIdx.x < nw) ? sm[threadIdx.x] : 0.0;
#pragma unroll
    for (int o = 16; o > 0; o >>= 1) r += __shfl_xor_sync(0xffffffffu, r, o);
    if (threadIdx.x == 0) sm[0] = r;
    __syncthreads();
    r = sm[0];
    __syncthreads();
    return r;
}

__device__ __forceinline__ float rsqrt_exact(float x) {
    return __fdiv_rn(1.0f, __fsqrt_rn(x));
}

// ---------------------------------------------------------------------------
// VALUE-PATH GEMM: 128x64 tile, 8x4 micro-tile, fp32, register double-buffer.
// ---------------------------------------------------------------------------
template<bool BT>
__global__ __launch_bounds__(256)
void gemm_kernel(const float* __restrict__ A, const float* __restrict__ B,
                 float* __restrict__ C,
                 int M, int N, int K, int lda, int ldb, int ldc,
                 long long sA, long long sB, long long sC) {
    __shared__ float As[16 * 132];
    __shared__ float Bs[16 * 68];
    long long bz = blockIdx.z;
    A += bz * sA; B += bz * sB; C += bz * sC;
    int m0 = blockIdx.y * 128, n0 = blockIdx.x * 64;
    int tid = threadIdx.x;
    int tx = tid & 15, ty = tid >> 4;

    float acc[8][4];
#pragma unroll
    for (int i = 0; i < 8; i++)
#pragma unroll
        for (int j = 0; j < 4; j++) acc[i][j] = 0.f;

    float4 ra[2], rb;
#pragma unroll
    for (int i = 0; i < 2; i++) {
        int e = tid + i * 256;
        int kg = (e & 3) << 2, m = e >> 2;
        ra[i] = make_float4(0.f, 0.f, 0.f, 0.f);
        if (m0 + m < M)
            ra[i] = *reinterpret_cast<const float4*>(&A[(long long)(m0 + m) * lda + kg]);
    }
    if (BT) {
        int kg = (tid & 3) << 2, n = tid >> 2;
        rb = make_float4(0.f, 0.f, 0.f, 0.f);
        if (n0 + n < N)
            rb = *reinterpret_cast<const float4*>(&B[(long long)(n0 + n) * ldb + kg]);
    } else {
        int ng = (tid & 15) << 2, kk = tid >> 4;
        rb = make_float4(0.f, 0.f, 0.f, 0.f);
        if (n0 + ng < N)
            rb = *reinterpret_cast<const float4*>(&B[(long long)kk * ldb + n0 + ng]);
    }

    for (int k0 = 0; k0 < K; k0 += 16) {
#pragma unroll
        for (int i = 0; i < 2; i++) {
            int e = tid + i * 256;
            int kg = (e & 3) << 2, m = e >> 2;
            As[(kg + 0) * 132 + m] = ra[i].x;
            As[(kg + 1) * 132 + m] = ra[i].y;
            As[(kg + 2) * 132 + m] = ra[i].z;
            As[(kg + 3) * 132 + m] = ra[i].w;
        }
        if (BT) {
            int kg = (tid & 3) << 2, n = tid >> 2;
            Bs[(kg + 0) * 68 + n] = rb.x;
            Bs[(kg + 1) * 68 + n] = rb.y;
            Bs[(kg + 2) * 68 + n] = rb.z;
            Bs[(kg + 3) * 68 + n] = rb.w;
        } else {
            int ng = (tid & 15) << 2, kk = tid >> 4;
            *reinterpret_cast<float4*>(&Bs[kk * 68 + ng]) = rb;
        }
        __syncthreads();
        int kn = k0 + 16;
        if (kn < K) {
#pragma unroll
            for (int i = 0; i < 2; i++) {
                int e = tid + i * 256;
                int kg = (e & 3) << 2, m = e >> 2;
                ra[i] = make_float4(0.f, 0.f, 0.f, 0.f);
                if (m0 + m < M)
                    ra[i] = *reinterpret_cast<const float4*>(&A[(long long)(m0 + m) * lda + kn + kg]);
            }
            if (BT) {
                int kg = (tid & 3) << 2, n = tid >> 2;
                rb = make_float4(0.f, 0.f, 0.f, 0.f);
                if (n0 + n < N)
                    rb = *reinterpret_cast<const float4*>(&B[(long long)(n0 + n) * ldb + kn + kg]);
            } else {
                int ng = (tid & 15) << 2, kk = tid >> 4;
                rb = make_float4(0.f, 0.f, 0.f, 0.f);
                if (n0 + ng < N)
                    rb = *reinterpret_cast<const float4*>(&B[(long long)(kn + kk) * ldb + n0 + ng]);
            }
        }
#pragma unroll
        for (int kk = 0; kk < 16; kk++) {
            float4 a0 = *reinterpret_cast<const float4*>(&As[kk * 132 + ty * 8]);
            float4 a1 = *reinterpret_cast<const float4*>(&As[kk * 132 + ty * 8 + 4]);
            float4 b4 = *reinterpret_cast<const float4*>(&Bs[kk * 68 + tx * 4]);
            float a[8] = {a0.x, a0.y, a0.z, a0.w, a1.x, a1.y, a1.z, a1.w};
            float b[4] = {b4.x, b4.y, b4.z, b4.w};
#pragma unroll
            for (int i = 0; i < 8; i++)
#pragma unroll
                for (int j = 0; j < 4; j++)
                    acc[i][j] = fmaf(a[i], b[j], acc[i][j]);
        }
        __syncthreads();
    }
#pragma unroll
    for (int i = 0; i < 8; i++) {
        int m = m0 + ty * 8 + i;
        if (m >= M) continue;
        int n = n0 + tx * 4;
        if (n + 3 < N) {
            *reinterpret_cast<float4*>(&C[(long long)m * ldc + n]) =
                make_float4(acc[i][0], acc[i][1], acc[i][2], acc[i][3]);
        } else {
#pragma unroll
            for (int j = 0; j < 4; j++)
                if (n + j < N) C[(long long)m * ldc + n + j] = acc[i][j];
        }
    }
}

// ---------------------------------------------------------------------------
// 64x64 GEMM, 4x4 micro-tile, register double-buffer.
//   CHUNKD=true : fp32 chains over 32-k chunks folded into doubles (score path)
// B is [N,K] row-major.
// ---------------------------------------------------------------------------
template<bool CHUNKD>
__global__ __launch_bounds__(256)
void gemm64_kernel(const float* __restrict__ A, const float* __restrict__ B,
                   float* __restrict__ C,
                   int M, int N, int K, int lda, int ldb, int ldc) {
    __shared__ float As[16 * 68];
    __shared__ float Bs[16 * 68];
    int m0 = blockIdx.y * 64, n0 = blockIdx.x * 64;
    int tid = threadIdx.x;
    int tx = tid & 15, ty = tid >> 4;

    float  accf[4][4];
    double accd[4][4];
#pragma unroll
    for (int i = 0; i < 4; i++)
#pragma unroll
        for (int j = 0; j < 4; j++) { accf[i][j] = 0.f; accd[i][j] = 0.0; }

    int kg = (tid & 3) << 2, mrow = tid >> 2;
    float4 ra, rb;
    ra = make_float4(0.f, 0.f, 0.f, 0.f);
    if (m0 + mrow < M)
        ra = *reinterpret_cast<const float4*>(&A[(long long)(m0 + mrow) * lda + kg]);
    rb = make_float4(0.f, 0.f, 0.f, 0.f);
    if (n0 + mrow < N)
        rb = *reinterpret_cast<const float4*>(&B[(long long)(n0 + mrow) * ldb + kg]);

    for (int k0 = 0; k0 < K; k0 += 16) {
        As[(kg + 0) * 68 + mrow] = ra.x;
        As[(kg + 1) * 68 + mrow] = ra.y;
        As[(kg + 2) * 68 + mrow] = ra.z;
        As[(kg + 3) * 68 + mrow] = ra.w;
        Bs[(kg + 0) * 68 + mrow] = rb.x;
        Bs[(kg + 1) * 68 + mrow] = rb.y;
        Bs[(kg + 2) * 68 + mrow] = rb.z;
        Bs[(kg + 3) * 68 + mrow] = rb.w;
        __syncthreads();
        int kn = k0 + 16;
        if (kn < K) {
            ra = make_float4(0.f, 0.f, 0.f, 0.f);
            if (m0 + mrow < M)
                ra = *reinterpret_cast<const float4*>(&A[(long long)(m0 + mrow) * lda + kn + kg]);
            rb = make_float4(0.f, 0.f, 0.f, 0.f);
            if (n0 + mrow < N)
                rb = *reinterpret_cast<const float4*>(&B[(long long)(n0 + mrow) * ldb + kn + kg]);
        }
#pragma unroll
        for (int kk = 0; kk < 16; kk++) {
            float4 a4 = *reinterpret_cast<const float4*>(&As[kk * 68 + ty * 4]);
            float4 b4 = *reinterpret_cast<const float4*>(&Bs[kk * 68 + tx * 4]);
            float a[4] = {a4.x, a4.y, a4.z, a4.w};
            float b[4] = {b4.x, b4.y, b4.z, b4.w};
#pragma unroll
            for (int i = 0; i < 4; i++)
#pragma unroll
                for (int j = 0; j < 4; j++)
                    accf[i][j] = fmaf(a[i], b[j], accf[i][j]);
        }
        if (CHUNKD && ((k0 >> 4) & 1)) {
#pragma unroll
            for (int i = 0; i < 4; i++)
#pragma unroll
                for (int j = 0; j < 4; j++) {
                    accd[i][j] += (double)accf[i][j];
                    accf[i][j] = 0.f;
                }
        }
        __syncthreads();
    }
#pragma unroll
    for (int i = 0; i < 4; i++) {
        int m = m0 + ty * 4 + i;
        if (m >= M) continue;
        int n = n0 + tx * 4;
        float o0 = CHUNKD ? (float)accd[i][0] : accf[i][0];
        float o1 = CHUNKD ? (float)accd[i][1] : accf[i][1];
        float o2 = CHUNKD ? (float)accd[i][2] : accf[i][2];
        float o3 = CHUNKD ? (float)accd[i][3] : accf[i][3];
        if (n + 3 < N) {
            *reinterpret_cast<float4*>(&C[(long long)m * ldc + n]) = make_float4(o0, o1, o2, o3);
        } else {
            if (n + 0 < N) C[(long long)m * ldc + n + 0] = o0;
            if (n + 1 < N) C[(long long)m * ldc + n + 1] = o1;
            if (n + 2 < N) C[(long long)m * ldc + n + 2] = o2;
            if (n + 3 < N) C[(long long)m * ldc + n + 3] = o3;
        }
    }
}

// ---------------------------------------------------------------------------
// RMSNorm rows in-place (fp64 stats, exact f32 epilogue)
// ---------------------------------------------------------------------------
__global__ void rms_kernel(float* x, const float* __restrict__ g, int N) {
    __shared__ double sm[8];
    int t = blockIdx.x;
    float* row = x + (size_t)t * N;
    double s = 0.0;
    for (int i = threadIdx.x; i < N; i += blockDim.x) { double v = row[i]; s += v * v; }
    s = block_reduce_sum_d(s, sm);
    float mean = __fdiv_rn((float)s, (float)N);
    float inv = rsqrt_exact(__fadd_rn(mean, 1e-6f));
    for (int i = threadIdx.x; i < N; i += blockDim.x)
        row[i] = __fmul_rn(__fmul_rn(row[i], inv), g[i]);
}

// ---------------------------------------------------------------------------
// Build skv[1025][576]
// ---------------------------------------------------------------------------
__global__ void kv_kernel(const float* __restrict__ ckv, const float* __restrict__ g,
                          const float* __restrict__ cosb, const float* __restrict__ sinb,
                          float* __restrict__ skv) {
    int t = blockIdx.x;
    if (t == TT) {
        for (int i = threadIdx.x; i < 576; i += blockDim.x) skv[(size_t)TT * 576 + i] = 0.f;
        return;
    }
    __shared__ double sm[8];
    const float* row = ckv + (size_t)t * 576;
    double s = 0.0;
    for (int i = threadIdx.x; i < 512; i += blockDim.x) { double v = row[i]; s += v * v; }
    s = block_reduce_sum_d(s, sm);
    float mean = __fdiv_rn((float)s, 512.f);
    float inv = rsqrt_exact(__fadd_rn(mean, 1e-6f));
    for (int i = threadIdx.x; i < 512; i += blockDim.x)
        skv[(size_t)t * 576 + i] = __fmul_rn(__fmul_rn(row[i], inv), g[i]);
    if (threadIdx.x < 64) {
        int i = threadIdx.x;
        float c = cosb[t * 64 + i], sn = sinb[t * 64 + i];
        float o;
        if (i < 32) o = __fsub_rn(__fmul_rn(row[512 + 2 * i], c), __fmul_rn(row[512 + 2 * i + 1], sn));
        else { int j = i - 32; o = __fadd_rn(__fmul_rn(row[512 + 2 * j + 1], c), __fmul_rn(row[512 + 2 * j], sn)); }
        skv[(size_t)t * 576 + 512 + i] = o;
    }
}

// ---------------------------------------------------------------------------
// In-place rope on first 64 dims of each 128-dim indexer head
// ---------------------------------------------------------------------------
__global__ void qirope_kernel(float* qi, const float* __restrict__ cosb,
                              const float* __restrict__ sinb) {
    int t = blockIdx.x;
    int h = threadIdx.x >> 5, lane = threadIdx.x & 31;
    float* p = qi + (size_t)t * 2048 + h * 128;
    float x0 = p[2 * lane], x1 = p[2 * lane + 1];
    float c0 = cosb[t * 64 + lane], s0 = sinb[t * 64 + lane];
    float c1 = cosb[t * 64 + 32 + lane], s1 = sinb[t * 64 + 32 + lane];
    __syncwarp();
    p[lane]      = __fsub_rn(__fmul_rn(x0, c0), __fmul_rn(x1, s0));
    p[lane + 32] = __fadd_rn(__fmul_rn(x1, c1), __fmul_rn(x0, s1));
}

// ---------------------------------------------------------------------------
// In-place LayerNorm(128)+rope on ki rows (fp64 stats, exact f32 epilogue)
// ---------------------------------------------------------------------------
__global__ void ki_kernel(float* ki, const float* __restrict__ w, const float* __restrict__ b,
                          const float* __restrict__ cosb, const float* __restrict__ sinb) {
    __shared__ double sm[8];
    __shared__ float srow[128];
    int t = blockIdx.x, d = threadIdx.x;
    float* row = ki + (size_t)t * 128;
    float v = row[d];
    double msum = block_reduce_sum_d((double)v, sm);
    float m = __fdiv_rn((float)msum, 128.f);
    float dv = __fsub_rn(v, m);
    double vsum = block_reduce_sum_d((double)dv * (double)dv, sm);
    float var = __fdiv_rn((float)vsum, 128.f);
    float inv = rsqrt_exact(__fadd_rn(var, 1e-6f));
    float y = __fadd_rn(__fmul_rn(__fmul_rn(dv, inv), w[d]), b[d]);
    srow[d] = y;
    __syncthreads();
    float o;
    if (d < 32)
        o = __fsub_rn(__fmul_rn(srow[2 * d], cosb[t * 64 + d]), __fmul_rn(srow[2 * d + 1], sinb[t * 64 + d]));
    else if (d < 64) {
        int j = d - 32;
        o = __fadd_rn(__fmul_rn(srow[2 * j + 1], cosb[t * 64 + d]), __fmul_rn(srow[2 * j], sinb[t * 64 + d]));
    } else o = y;
    row[d] = o;
}

// ---------------------------------------------------------------------------
// Indexer score: 8 t per block, causal skip.
// ---------------------------------------------------------------------------
__global__ __launch_bounds__(256)
void score_kernel(const float* __restrict__ qi, const float* __restrict__ ki,
                  const float* __restrict__ wproj,
                  const int* __restrict__ ks, const int* __restrict__ ke,
                  float* __restrict__ score) {
    __shared__ float s_qi[16 * 132];
    __shared__ float s_ki[16 * 132];
    __shared__ float s_prod[16 * 16];
    int s0 = blockIdx.x * 16;
    int h = threadIdx.x & 15, sl = threadIdx.x >> 4;
    bool ki_loaded = false;
    for (int tt = 0; tt < 8; tt++) {
        int t = blockIdx.y * 8 + tt;
        int kst = ks[t], ket = ke[t];
        if (ket - kst + 1 <= TOPK) continue;
        if (s0 > ket || s0 + 15 < kst) {
            if (threadIdx.x < 16)
                score[(size_t)t * TT + s0 + threadIdx.x] = NEGF;
            continue;
        }
        if (!ki_loaded) {
#pragma unroll
            for (int i = 0; i < 2; i++) {
                int e = threadIdx.x + i * 256;
                int r = e >> 5, c4 = (e & 31) << 2;
                *reinterpret_cast<float4*>(&s_ki[r * 132 + c4]) =
                    *reinterpret_cast<const float4*>(&ki[(size_t)(s0 + r) * 128 + c4]);
            }
            ki_loaded = true;
        }
        __syncthreads();
#pragma unroll
        for (int i = 0; i < 2; i++) {
            int e = threadIdx.x + i * 256;
            int r = e >> 5, c4 = (e & 31) << 2;
            *reinterpret_cast<float4*>(&s_qi[r * 132 + c4]) =
                *reinterpret_cast<const float4*>(&qi[(size_t)t * 2048 + r * 128 + c4]);
        }
        __syncthreads();
        double acc = 0.0;
#pragma unroll
        for (int c0 = 0; c0 < 128; c0 += 32) {
            float tacc = 0.f;
#pragma unroll
            for (int d4 = 0; d4 < 8; d4++) {
                float4 q4 = *reinterpret_cast<const float4*>(&s_qi[h * 132 + c0 + d4 * 4]);
                float4 k4 = *reinterpret_cast<const float4*>(&s_ki[sl * 132 + c0 + d4 * 4]);
                tacc = fmaf(q4.x, k4.x, tacc);
                tacc = fmaf(q4.y, k4.y, tacc);
                tacc = fmaf(q4.z, k4.z, tacc);
                tacc = fmaf(q4.w, k4.w, tacc);
            }
            acc += (double)tacc;
        }
        float lg = (float)acc;
        s_prod[sl * 16 + h] = __fmul_rn(fmaxf(lg, 0.f), wproj[t * 16 + h]);
        __syncthreads();
        if (threadIdx.x < 16) {
            int s = s0 + threadIdx.x;
            double sum = 0.0;
#pragma unroll
            for (int hh = 0; hh < 16; hh++) sum += (double)s_prod[threadIdx.x * 16 + hh];
            float sc = __fmul_rn((float)sum, 0.022097086912079608f);
            if (s < kst || s > ket) sc = NEGF;
            score[(size_t)t * TT + s] = sc;
        }
    }
}

// ---------------------------------------------------------------------------
// Top-256 per row; trivial rows short-circuited; variable-size bitonic sort
// (n=512 when ke<512: entries >ke are exactly NEGF and cannot enter top-256
//  since nvalid>256, so sorting the 512-prefix is set-exact).
// ---------------------------------------------------------------------------
__global__ __launch_bounds__(512)
void topk_kernel(const float* __restrict__ score, const int* __restrict__ ks,
                 const int* __restrict__ ke, int* __restrict__ out) {
    __shared__ unsigned long long keys[TT];
    int t = blockIdx.x;
    int kst = ks[t], ket = ke[t];
    int nvalid = ket - kst + 1;
    if (nvalid <= TOPK) {
        if (threadIdx.x < TOPK) {
            int j = threadIdx.x;
            out[t * TOPK + j] = (j < nvalid) ? (kst + j) : TT;
        }
        return;
    }
    int n = (ket < 512) ? 512 : TT;
    const float* row = score + (size_t)t * TT;
    for (int i = threadIdx.x; i < n; i += 512) {
        unsigned u = __float_as_uint(row[i]);
        if (u == 0x80000000u) u = 0u;
        u = (u & 0x80000000u) ? ~u : (u | 0x80000000u);
        keys[i] = ((unsigned long long)(~u) << 32) | (unsigned)i;
    }
    __syncthreads();
    for (int k = 2; k <= n; k <<= 1) {
        for (int j = k >> 1; j > 0; j >>= 1) {
            for (int i = threadIdx.x; i < n; i += 512) {
                int ixj = i ^ j;
                if (ixj > i) {
                    bool up = ((i & k) == 0);
                    unsigned long long a = keys[i], c = keys[ixj];
                    if ((a > c) == up) { keys[i] = c; keys[ixj] = a; }
                }
            }
            __syncthreads();
        }
    }
    if (threadIdx.x < TOPK) {
        int idx = (int)(keys[threadIdx.x] & 0xffffffffu);
        float v = score[(size_t)t * TT + idx];
        out[t * TOPK + threadIdx.x] = (v <= -5e29f) ? TT : idx;
    }
}

// ---------------------------------------------------------------------------
// Fill sq[t,h,512:576] = rope(q_full[t, h*192+128 : h*192+192])
// ---------------------------------------------------------------------------
__global__ void sqrope_kernel(const float* __restrict__ qfull, const float* __restrict__ cosb,
                              const float* __restrict__ sinb, float* __restrict__ sq) {
    int t = blockIdx.x;
    int h = threadIdx.x >> 5, lane = threadIdx.x & 31;
    const float* p = qfull + (size_t)t * 3072 + h * 192 + 128;
    float x0 = p[2 * lane], x1 = p[2 * lane + 1];
    float* o = sq + ((size_t)t * 16 + h) * 576 + 512;
    o[lane]      = __fsub_rn(__fmul_rn(x0, cosb[t * 64 + lane]), __fmul_rn(x1, sinb[t * 64 + lane]));
    o[lane + 32] = __fadd_rn(__fmul_rn(x1, cosb[t * 64 + 32 + lane]), __fmul_rn(x0, sinb[t * 64 + 32 + lane]));
}

// ---------------------------------------------------------------------------
// Gathered sparse attention — online softmax + register-prefetched KV gather.
// (R13-proven layout: stride 580, no swizzle)
// ---------------------------------------------------------------------------
#define ATT_SMEM ((16*580*2) * 4 + 256 * 4)
__global__ __launch_bounds__(256, 2)
void attn_kernel(const float* __restrict__ sq, const float* __restrict__ skv,
                 const int* __restrict__ idxs, float* __restrict__ out) {
    extern __shared__ float sm[];
    float* s_sq = sm;
    float* s_kv = sm + 16 * 580;
    int*   s_idx = (int*)(sm + 2 * 16 * 580);
    int t = blockIdx.x, tid = threadIdx.x;
    int h = tid >> 4, q = tid & 15;

    s_idx[tid] = idxs[t * TOPK + tid];
#pragma unroll
    for (int i = 0; i < 9; i++) {
        int e = tid + i * 256;
        int r = e / 144, c4 = (e % 144) << 2;
        *reinterpret_cast<float4*>(&s_sq[r * 580 + c4]) =
            *reinterpret_cast<const float4*>(&sq[(size_t)t * 9216 + r * 576 + c4]);
    }
    __syncthreads();

    float4 pre[9];
#pragma unroll
    for (int i = 0; i < 9; i++) {
        int e = tid + i * 256;
        int r = e / 144, c4 = (e % 144) << 2;
        int gi = s_idx[r];
        pre[i] = *reinterpret_cast<const float4*>(&skv[(size_t)gi * 576 + c4]);
    }

    const float qscale = 0.07216878364870323f;
    float m_run = NEGF, s_run = 0.f;
    float acc2[32];
#pragma unroll
    for (int i = 0; i < 32; i++) acc2[i] = 0.f;
    unsigned base16 = tid & 16;

    for (int jb = 0; jb < 16; jb++) {
        __syncthreads();
#pragma unroll
        for (int i = 0; i < 9; i++) {
            int e = tid + i * 256;
            int r = e / 144, c4 = (e % 144) << 2;
            *reinterpret_cast<float4*>(&s_kv[r * 580 + c4]) = pre[i];
        }
        if (jb < 15) {
#pragma unroll
            for (int i = 0; i < 9; i++) {
                int e = tid + i * 256;
                int r = e / 144, c4 = (e % 144) << 2;
                int gi = s_idx[(jb + 1) * 16 + r];
                pre[i] = *reinterpret_cast<const float4*>(&skv[(size_t)gi * 576 + c4]);
            }
        }
        __syncthreads();
        float acc = 0.f;
#pragma unroll 4
        for (int d4 = 0; d4 < 144; d4++) {
            float4 qv = *reinterpret_cast<const float4*>(&s_sq[h * 580 + (d4 << 2)]);
            float4 kv = *reinterpret_cast<const float4*>(&s_kv[q * 580 + (d4 << 2)]);
            acc = fmaf(qv.x, kv.x, acc);
            acc = fmaf(qv.y, kv.y, acc);
            acc = fmaf(qv.z, kv.z, acc);
            acc = fmaf(qv.w, kv.w, acc);
        }
        float l = (s_idx[jb * 16 + q] == TT) ? NEGF : acc * qscale;
        float mt = l;
#pragma unroll
        for (int o = 8; o > 0; o >>= 1) mt = fmaxf(mt, __shfl_xor_sync(0xffffffffu, mt, o, 16));
        float m_new = fmaxf(m_run, mt);
        float scale = __expf(m_run - m_new);
        float p = __expf(l - m_new);
        float ps = p;
#pragma unroll
        for (int o = 8; o > 0; o >>= 1) ps += __shfl_xor_sync(0xffffffffu, ps, o, 16);
        s_run = s_run * scale + ps;
        m_run = m_new;
#pragma unroll
        for (int i = 0; i < 32; i++) acc2[i] *= scale;
#pragma unroll 2
        for (int jj = 0; jj < 16; jj++) {
            float pj = __shfl_sync(0xffffffffu, p, base16 + jj, 32);
#pragma unroll
            for (int g = 0; g < 8; g++) {
                float4 kv = *reinterpret_cast<const float4*>(&s_kv[jj * 580 + g * 64 + (q << 2)]);
                acc2[g * 4 + 0] = fmaf(pj, kv.x, acc2[g * 4 + 0]);
                acc2[g * 4 + 1] = fmaf(pj, kv.y, acc2[g * 4 + 1]);
                acc2[g * 4 + 2] = fmaf(pj, kv.z, acc2[g * 4 + 2]);
                acc2[g * 4 + 3] = fmaf(pj, kv.w, acc2[g * 4 + 3]);
            }
        }
    }
    float inv = 1.f / s_run;
    size_t base = ((size_t)t * 16 + h) * 512;
#pragma unroll
    for (int g = 0; g < 8; g++) {
        float4 o = make_float4(acc2[g * 4 + 0] * inv, acc2[g * 4 + 1] * inv,
                               acc2[g * 4 + 2] * inv, acc2[g * 4 + 3] * inv);
        *reinterpret_cast<float4*>(&out[base + g * 64 + (q << 2)]) = o;
    }
}

// ---------------------------------------------------------------------------
// Host launcher — DAG fork/join over 3 streams
// ---------------------------------------------------------------------------
extern "C" void kernel_launch(void* const* d_in, const int* in_sizes, int n_in,
                              void* d_out, int out_size) {
    const float* hidden  = (const float*)d_in[0];
    const float* cosb    = (const float*)d_in[1];
    const float* sinb    = (const float*)d_in[2];
    const int*   ks      = (const int*)d_in[3];
    const int*   ke      = (const int*)d_in[4];
    const float* w_qa    = (const float*)d_in[5];
    const float* g_qa    = (const float*)d_in[6];
    const float* w_qb    = (const float*)d_in[7];
    const float* w_kva   = (const float*)d_in[8];
    const float* g_kva   = (const float*)d_in[9];
    const float* w_kvb   = (const float*)d_in[10];
    const float* w_o     = (const float*)d_in[11];
    const float* i_wqb   = (const float*)d_in[12];
    const float* i_wk    = (const float*)d_in[13];
    const float* i_ln_w  = (const float*)d_in[14];
    const float* i_ln_b  = (const float*)d_in[15];
    const float* i_wproj = (const float*)d_in[16];
    float* out = (float*)d_out;

    void* basev = nullptr;
    cudaGetSymbolAddress(&basev, g_scratch);
    float* base = (float*)basev;
    float* qlat   = base + OFF_QLAT;
    float* ckv    = base + OFF_CKV;
    float* skv    = base + OFF_SKV;
    float* qi     = base + OFF_QI;
    float* ki     = base + OFF_KI;
    float* wbuf   = base + OFF_W;
    float* score  = base + OFF_SCORE;
    int*   idxb   = (int*)(base + OFF_IDX);
    float* qfull  = base + OFF_QFULL;
    float* sq     = base + OFF_SQ;
    float* attnb  = base + OFF_ATTN;
    float* obuf   = base + OFF_O;

    cudaFuncSetAttribute(attn_kernel, cudaFuncAttributeMaxDynamicSharedMemorySize, ATT_SMEM);

    cudaStream_t s0 = 0;
    cudaStream_t s1 = g_sp.s1, s2 = g_sp.s2;
    dim3 blk(256);

    // fork
    cudaEventRecord(g_sp.e_start, s0);
    cudaStreamWaitEvent(s1, g_sp.e_start, 0);
    cudaStreamWaitEvent(s2, g_sp.e_start, 0);

    // --- s2: indexer K/W + KV branch ---
    gemm64_kernel<true><<<dim3(2, 16), blk, 0, s2>>>(hidden, i_wk, ki, 1024, 128, 2048,
                                                     2048, 2048, 128);
    ki_kernel<<<1024, 128, 0, s2>>>(ki, i_ln_w, i_ln_b, cosb, sinb);
    gemm64_kernel<true><<<dim3(1, 16), blk, 0, s2>>>(hidden, i_wproj, wbuf, 1024, 16, 2048,
                                                     2048, 2048, 16);
    cudaEventRecord(g_sp.e_ki, s2);
    gemm64_kernel<false><<<dim3(9, 16), blk, 0, s2>>>(hidden, w_kva, ckv, 1024, 576, 2048,
                                                      2048, 2048, 576);
    kv_kernel<<<1025, 256, 0, s2>>>(ckv, g_kva, cosb, sinb, skv);
    cudaEventRecord(g_sp.e_kv, s2);

    // --- s0: qlat (critical path) ---
    gemm64_kernel<true><<<dim3(24, 16), blk, 0, s0>>>(hidden, w_qa, qlat, 1024, 1536, 2048,
                                                      2048, 2048, 1536);
    rms_kernel<<<1024, 256, 0, s0>>>(qlat, g_qa, 1536);
    cudaEventRecord(g_sp.e_qlat, s0);

    // --- s1: q_full branch ---
    cudaStreamWaitEvent(s1, g_sp.e_qlat, 0);
    gemm_kernel<true><<<dim3(48, 8, 1), blk, 0, s1>>>(qlat, w_qb, qfull, 1024, 3072, 1536,
                                                      1536, 1536, 3072, 0, 0, 0);
    gemm_kernel<false><<<dim3(8, 8, 16), blk, 0, s1>>>(qfull, w_kvb, sq, 1024, 512, 128,
                                                       3072, 512, 9216,
                                                       192, 256 * 512, 576);
    sqrope_kernel<<<1024, 512, 0, s1>>>(qfull, cosb, sinb, sq);
    cudaEventRecord(g_sp.e_sq, s1);

    // --- s0: qi -> score -> topk ---
    gemm64_kernel<true><<<dim3(32, 16), blk, 0, s0>>>(qlat, i_wqb, qi, 1024, 2048, 1536,
                                                      1536, 1536, 2048);
    qirope_kernel<<<1024, 512, 0, s0>>>(qi, cosb, sinb);
    cudaStreamWaitEvent(s0, g_sp.e_ki, 0);
    score_kernel<<<dim3(64, 128), blk, 0, s0>>>(qi, ki, wbuf, ks, ke, score);
    topk_kernel<<<1024, 512, 0, s0>>>(score, ks, ke, idxb);

    // --- join: attention + output projections ---
    cudaStreamWaitEvent(s0, g_sp.e_kv, 0);
    cudaStreamWaitEvent(s0, g_sp.e_sq, 0);
    attn_kernel<<<1024, 256, ATT_SMEM, s0>>>(sq, skv, idxb, attnb);
    gemm_kernel<true><<<dim3(2, 8, 16), blk, 0, s0>>>(attnb, w_kvb + 128 * 512, obuf,
                                                      1024, 128, 512,
                                                      8192, 512, 2048,
                                                      512, 256 * 512, 128);
    gemm_kernel<true><<<dim3(32, 8, 1), blk, 0, s0>>>(obuf, w_o, out, 1024, 2048, 2048,
                                                      2048, 2048, 2048, 0, 0, 0);
}